// round 1
// baseline (speedup 1.0000x reference)
#include <cuda_runtime.h>
#include <cstdint>

#define B_    64
#define S_    4096
#define F_    64
#define G4_   256   // 4 * F_

// ---------------- scratch (no cudaMalloc allowed) ----------------
__device__ float g_bufA[(size_t)B_ * S_ * F_];    // conv0 out / conv2 out
__device__ float g_bufB[(size_t)B_ * S_ * F_];    // conv1 out / h0 sequence
__device__ float g_xw[(size_t)B_ * S_ * G4_];     // gate pre-activations (reused layer0/layer1)
__device__ float g_cfinal[B_ * F_];

// ---------------- packed f32x2 helpers (sm_103a FFMA2 path) ----------------
__device__ __forceinline__ unsigned long long fma2(unsigned long long a,
                                                   unsigned long long b,
                                                   unsigned long long c) {
    unsigned long long d;
    asm("fma.rn.f32x2 %0, %1, %2, %3;" : "=l"(d) : "l"(a), "l"(b), "l"(c));
    return d;
}
__device__ __forceinline__ unsigned long long add2(unsigned long long a,
                                                   unsigned long long b) {
    unsigned long long d;
    asm("add.rn.f32x2 %0, %1, %2;" : "=l"(d) : "l"(a), "l"(b));
    return d;
}
__device__ __forceinline__ unsigned long long dup2(float a) {
    unsigned long long d;
    asm("mov.b64 %0, {%1, %1};" : "=l"(d) : "f"(a));
    return d;
}
__device__ __forceinline__ unsigned long long pk2(float lo, float hi) {
    unsigned long long d;
    asm("mov.b64 %0, {%1, %2};" : "=l"(d) : "f"(lo), "f"(hi));
    return d;
}
__device__ __forceinline__ float2 upk2(unsigned long long v) {
    float2 r;
    asm("mov.b64 {%0, %1}, %2;" : "=f"(r.x), "=f"(r.y) : "l"(v));
    return r;
}

__device__ __forceinline__ float sigmoid_f(float x) {
    return __fdividef(1.0f, 1.0f + __expf(-x));
}
__device__ __forceinline__ float tanh_f(float x) {
    return __fdividef(2.0f, 1.0f + __expf(-2.0f * x)) - 1.0f;
}

// ---------------------------------------------------------------------------
// Fused conv1d / GEMM kernel.
//   KW=3: out[b,s,co] = bias[co] + sum_{dk,ci} x[b, s+dk-1, ci] * w[dk,ci,co]
//   KW=1: plain GEMM  out = x @ w + bias   (used for x@Wx LSTM input projections)
// Block: 256 threads = 16(tx: cout/4) x 16(ty: s/4); each thread computes a
// 4x4 (s x cout) micro-tile with packed f32x2 FMAs on cout pairs.
// Grid: (S/64, Cout/64, B)
// ---------------------------------------------------------------------------
template <int KW, bool RELU>
__global__ void __launch_bounds__(256)
conv_gemm(const float* __restrict__ xin, const float* __restrict__ w,
          const float* __restrict__ bias, float* __restrict__ out,
          int Cin, int Cout) {
    constexpr int PAD = KW / 2;
    constexpr int RX = 64 + KW - 1;   // input rows needed per s-tile

    __shared__ __align__(16) float xs[66][16];
    __shared__ __align__(16) float ws[KW][16][64];

    const int tid = threadIdx.x;
    const int tx = tid & 15;          // cout quad
    const int ty = tid >> 4;          // s quad
    const int s0 = blockIdx.x * 64;
    const int co0 = blockIdx.y * 64;
    const int b = blockIdx.z;

    const float* xb = xin + (size_t)b * S_ * Cin;

    unsigned long long a01[4], a23[4];
#pragma unroll
    for (int i = 0; i < 4; i++) { a01[i] = 0ull; a23[i] = 0ull; }

    for (int ck = 0; ck < Cin; ck += 16) {
        __syncthreads();
        // stage input slab [RX rows x 16 cin]
        for (int idx = tid; idx < RX * 16; idx += 256) {
            int r = idx >> 4, k = idx & 15;
            int sg = s0 + r - PAD;
            float v = 0.0f;
            if (sg >= 0 && sg < S_) v = xb[(size_t)sg * Cin + ck + k];
            xs[r][k] = v;
        }
        // stage weight slab [KW x 16 cin x 64 cout]
        for (int idx = tid; idx < KW * 16 * 64; idx += 256) {
            int c = idx & 63, k = (idx >> 6) & 15, dk = idx >> 10;
            ws[dk][k][c] = w[((size_t)dk * Cin + (ck + k)) * Cout + co0 + c];
        }
        __syncthreads();

#pragma unroll
        for (int dk = 0; dk < KW; dk++) {
#pragma unroll
            for (int k = 0; k < 16; k++) {
                ulonglong2 wv =
                    *reinterpret_cast<const ulonglong2*>(&ws[dk][k][tx << 2]);
#pragma unroll
                for (int i = 0; i < 4; i++) {
                    unsigned long long av = dup2(xs[ty * 4 + i + dk][k]);
                    a01[i] = fma2(av, wv.x, a01[i]);
                    a23[i] = fma2(av, wv.y, a23[i]);
                }
            }
        }
    }

    // epilogue: +bias, optional relu, float4 store
    const int c0 = co0 + (tx << 2);
    const float bb0 = bias[c0 + 0], bb1 = bias[c0 + 1];
    const float bb2 = bias[c0 + 2], bb3 = bias[c0 + 3];
#pragma unroll
    for (int i = 0; i < 4; i++) {
        float2 v01 = upk2(a01[i]);
        float2 v23 = upk2(a23[i]);
        float4 o;
        o.x = v01.x + bb0; o.y = v01.y + bb1;
        o.z = v23.x + bb2; o.w = v23.y + bb3;
        if (RELU) {
            o.x = fmaxf(o.x, 0.0f); o.y = fmaxf(o.y, 0.0f);
            o.z = fmaxf(o.z, 0.0f); o.w = fmaxf(o.w, 0.0f);
        }
        int sg = s0 + ty * 4 + i;
        *reinterpret_cast<float4*>(&out[((size_t)b * S_ + sg) * Cout + c0]) = o;
    }
}

// ---------------------------------------------------------------------------
// LSTM recurrence: one persistent block per batch element (64 blocks, 1/SM).
// 256 threads; thread g owns gate column g. Wh column is REGISTER-resident
// (32 packed f32x2 = 64 floats). Per step: packed dot over h (16 LDS.128 +
// 32 fma2), activation, SMEM gate exchange, c/h update by threads 0..63.
// xw = precomputed x@Wx + b, [B, S, 256]; prefetched 4 steps deep.
// ---------------------------------------------------------------------------
__global__ void __launch_bounds__(256, 1)
lstm_layer(const float* __restrict__ xw, const float* __restrict__ Wh,
           float* __restrict__ h_seq_out,   // [B,S,64] or nullptr
           float* __restrict__ c_final) {   // [B,64]   or nullptr
    const int b = blockIdx.x;
    const int g = threadIdx.x;
    const int gtype = g >> 6;   // 0:i 1:f 2:g 3:o

    __shared__ __align__(16) float h_s[F_];
    __shared__ float gbuf[G4_];

    // register-resident Wh column g, packed by k-pairs
    unsigned long long w2[32];
#pragma unroll
    for (int k2 = 0; k2 < 32; k2++) {
        float lo = Wh[(size_t)(2 * k2) * G4_ + g];
        float hi = Wh[(size_t)(2 * k2 + 1) * G4_ + g];
        w2[k2] = pk2(lo, hi);
    }

    if (g < F_) h_s[g] = 0.0f;
    float c_reg = 0.0f;

    const float* xwb = xw + (size_t)b * S_ * G4_ + g;
    float xwbuf[4];
#pragma unroll
    for (int j = 0; j < 4; j++) xwbuf[j] = xwb[(size_t)j * G4_];
    __syncthreads();

    const ulonglong2* h4 = reinterpret_cast<const ulonglong2*>(h_s);

    for (int t = 0; t < S_; t += 4) {
#pragma unroll
        for (int j = 0; j < 4; j++) {
            float xv = xwbuf[j];
            int tn = t + 4 + j;
            if (tn < S_) xwbuf[j] = xwb[(size_t)tn * G4_];   // prefetch 4 ahead

            unsigned long long acc0 = 0ull, acc1 = 0ull, acc2 = 0ull, acc3 = 0ull;
#pragma unroll
            for (int k4 = 0; k4 < 16; k4 += 2) {
                ulonglong2 hA = h4[k4];
                ulonglong2 hB = h4[k4 + 1];
                acc0 = fma2(hA.x, w2[2 * k4 + 0], acc0);
                acc1 = fma2(hA.y, w2[2 * k4 + 1], acc1);
                acc2 = fma2(hB.x, w2[2 * k4 + 2], acc2);
                acc3 = fma2(hB.y, w2[2 * k4 + 3], acc3);
            }
            acc0 = add2(acc0, acc1);
            acc2 = add2(acc2, acc3);
            acc0 = add2(acc0, acc2);
            float2 sv = upk2(acc0);
            float pre = sv.x + sv.y + xv;

            float gv = (gtype == 2) ? tanh_f(pre) : sigmoid_f(pre);
            gbuf[g] = gv;
            __syncthreads();

            if (g < F_) {
                float iv = gbuf[g];
                float fv = gbuf[g + 64];
                float gg = gbuf[g + 128];
                float ov = gbuf[g + 192];
                c_reg = fv * c_reg + iv * gg;
                float hv = ov * tanh_f(c_reg);
                h_s[g] = hv;
                if (h_seq_out)
                    h_seq_out[((size_t)b * S_ + (t + j)) * F_ + g] = hv;
            }
            __syncthreads();
        }
    }

    if (g < F_ && c_final) c_final[b * F_ + g] = c_reg;
}

// ---------------------------------------------------------------------------
// Tiny dense head: out[64,10] = c_final[64,64] @ dense_w[64,10] + dense_b
// ---------------------------------------------------------------------------
__global__ void dense_head(const float* __restrict__ cf,
                           const float* __restrict__ wd,
                           const float* __restrict__ bd,
                           float* __restrict__ out) {
    int t = threadIdx.x;
    if (t >= B_ * 10) return;
    int b = t / 10, n = t % 10;
    float s = bd[n];
#pragma unroll
    for (int k = 0; k < F_; k++) s += cf[b * F_ + k] * wd[k * 10 + n];
    out[b * 10 + n] = s;
}

// ---------------------------------------------------------------------------
extern "C" void kernel_launch(void* const* d_in, const int* in_sizes, int n_in,
                              void* d_out, int out_size) {
    const float* x       = (const float*)d_in[0];
    const float* conv_w0 = (const float*)d_in[1];
    const float* conv_b0 = (const float*)d_in[2];
    const float* conv_w1 = (const float*)d_in[3];
    const float* conv_b1 = (const float*)d_in[4];
    const float* conv_w2 = (const float*)d_in[5];
    const float* conv_b2 = (const float*)d_in[6];
    const float* Wx0     = (const float*)d_in[7];
    const float* Wh0     = (const float*)d_in[8];
    const float* b0      = (const float*)d_in[9];
    const float* Wx1     = (const float*)d_in[10];
    const float* Wh1     = (const float*)d_in[11];
    const float* b1      = (const float*)d_in[12];
    const float* dense_w = (const float*)d_in[13];
    const float* dense_b = (const float*)d_in[14];
    float* out = (float*)d_out;

    void *pA, *pB, *pXW, *pCF;
    cudaGetSymbolAddress(&pA, g_bufA);
    cudaGetSymbolAddress(&pB, g_bufB);
    cudaGetSymbolAddress(&pXW, g_xw);
    cudaGetSymbolAddress(&pCF, g_cfinal);
    float* bufA = (float*)pA;
    float* bufB = (float*)pB;
    float* xwb  = (float*)pXW;
    float* cfin = (float*)pCF;

    dim3 convGrid(S_ / 64, 1, B_);
    dim3 gemmGrid(S_ / 64, G4_ / 64, B_);

    // CNN stack
    conv_gemm<3, true><<<convGrid, 256>>>(x, conv_w0, conv_b0, bufA, 128, 64);
    conv_gemm<3, true><<<convGrid, 256>>>(bufA, conv_w1, conv_b1, bufB, 64, 64);
    conv_gemm<3, true><<<convGrid, 256>>>(bufB, conv_w2, conv_b2, bufA, 64, 64);

    // LSTM layer 0: input projection then recurrence (stores h sequence)
    conv_gemm<1, false><<<gemmGrid, 256>>>(bufA, Wx0, b0, xwb, 64, 256);
    lstm_layer<<<B_, 256>>>(xwb, Wh0, bufB, nullptr);

    // LSTM layer 1: projection of h0 sequence then recurrence (keeps final c)
    conv_gemm<1, false><<<gemmGrid, 256>>>(bufB, Wx1, b1, xwb, 64, 256);
    lstm_layer<<<B_, 256>>>(xwb, Wh1, nullptr, cfin);

    // Dense head
    dense_head<<<1, B_ * 10>>>(cfin, dense_w, dense_b, out);
}

// round 2
// speedup vs baseline: 1.4392x; 1.4392x over previous
#include <cuda_runtime.h>
#include <cstdint>

#define B_    64
#define S_    4096
#define F_    64
#define G4_   256   // 4 * F_

// ---------------- scratch (no cudaMalloc allowed) ----------------
__device__ float g_bufA[(size_t)B_ * S_ * F_];    // conv0 out / conv2 out
__device__ float g_bufB[(size_t)B_ * S_ * F_];    // conv1 out
__device__ float g_xw0[(size_t)B_ * S_ * G4_];    // layer0 gate pre-activations
__device__ float g_xw1[(size_t)B_ * S_ * G4_];    // layer1 gate pre-activations (produced on the fly)
__device__ int   g_prog[B_];                      // producer progress flags
__device__ float g_cfinal[B_ * F_];

typedef unsigned long long ull;

// ---------------- packed f32x2 helpers (sm_103a FFMA2 path) ----------------
__device__ __forceinline__ ull fma2(ull a, ull b, ull c) {
    ull d;
    asm("fma.rn.f32x2 %0, %1, %2, %3;" : "=l"(d) : "l"(a), "l"(b), "l"(c));
    return d;
}
__device__ __forceinline__ ull add2(ull a, ull b) {
    ull d;
    asm("add.rn.f32x2 %0, %1, %2;" : "=l"(d) : "l"(a), "l"(b));
    return d;
}
__device__ __forceinline__ ull dup2(float a) {
    ull d;
    asm("mov.b64 %0, {%1, %1};" : "=l"(d) : "f"(a));
    return d;
}
__device__ __forceinline__ ull pk2(float lo, float hi) {
    ull d;
    asm("mov.b64 %0, {%1, %2};" : "=l"(d) : "f"(lo), "f"(hi));
    return d;
}
__device__ __forceinline__ float2 upk2(ull v) {
    float2 r;
    asm("mov.b64 {%0, %1}, %2;" : "=f"(r.x), "=f"(r.y) : "l"(v));
    return r;
}

__device__ __forceinline__ float sigmoid_f(float x) {
    return __fdividef(1.0f, 1.0f + __expf(-x));
}
__device__ __forceinline__ float tanh_f(float x) {
    return __fdividef(2.0f, 1.0f + __expf(-2.0f * x)) - 1.0f;
}

// ---------------------------------------------------------------------------
// Fused conv1d / GEMM kernel (unchanged from R1).
// ---------------------------------------------------------------------------
template <int KW, bool RELU>
__global__ void __launch_bounds__(256)
conv_gemm(const float* __restrict__ xin, const float* __restrict__ w,
          const float* __restrict__ bias, float* __restrict__ out,
          int Cin, int Cout) {
    constexpr int PAD = KW / 2;
    constexpr int RX = 64 + KW - 1;

    __shared__ __align__(16) float xs[66][16];
    __shared__ __align__(16) float ws[KW][16][64];

    const int tid = threadIdx.x;
    const int tx = tid & 15;
    const int ty = tid >> 4;
    const int s0 = blockIdx.x * 64;
    const int co0 = blockIdx.y * 64;
    const int b = blockIdx.z;

    const float* xb = xin + (size_t)b * S_ * Cin;

    ull a01[4], a23[4];
#pragma unroll
    for (int i = 0; i < 4; i++) { a01[i] = 0ull; a23[i] = 0ull; }

    for (int ck = 0; ck < Cin; ck += 16) {
        __syncthreads();
        for (int idx = tid; idx < RX * 16; idx += 256) {
            int r = idx >> 4, k = idx & 15;
            int sg = s0 + r - PAD;
            float v = 0.0f;
            if (sg >= 0 && sg < S_) v = xb[(size_t)sg * Cin + ck + k];
            xs[r][k] = v;
        }
        for (int idx = tid; idx < KW * 16 * 64; idx += 256) {
            int c = idx & 63, k = (idx >> 6) & 15, dk = idx >> 10;
            ws[dk][k][c] = w[((size_t)dk * Cin + (ck + k)) * Cout + co0 + c];
        }
        __syncthreads();

#pragma unroll
        for (int dk = 0; dk < KW; dk++) {
#pragma unroll
            for (int k = 0; k < 16; k++) {
                ulonglong2 wv =
                    *reinterpret_cast<const ulonglong2*>(&ws[dk][k][tx << 2]);
#pragma unroll
                for (int i = 0; i < 4; i++) {
                    ull av = dup2(xs[ty * 4 + i + dk][k]);
                    a01[i] = fma2(av, wv.x, a01[i]);
                    a23[i] = fma2(av, wv.y, a23[i]);
                }
            }
        }
    }

    const int c0 = co0 + (tx << 2);
    const float bb0 = bias[c0 + 0], bb1 = bias[c0 + 1];
    const float bb2 = bias[c0 + 2], bb3 = bias[c0 + 3];
#pragma unroll
    for (int i = 0; i < 4; i++) {
        float2 v01 = upk2(a01[i]);
        float2 v23 = upk2(a23[i]);
        float4 o;
        o.x = v01.x + bb0; o.y = v01.y + bb1;
        o.z = v23.x + bb2; o.w = v23.y + bb3;
        if (RELU) {
            o.x = fmaxf(o.x, 0.0f); o.y = fmaxf(o.y, 0.0f);
            o.z = fmaxf(o.z, 0.0f); o.w = fmaxf(o.w, 0.0f);
        }
        int sg = s0 + ty * 4 + i;
        *reinterpret_cast<float4*>(&out[((size_t)b * S_ + sg) * Cout + c0]) = o;
    }
}

// ---------------------------------------------------------------------------
// Pipelined 2-layer LSTM recurrence.
// Grid: 128 blocks x 256 threads. Blocks 0..63 = layer0 producers (batch b),
// blocks 64..127 = layer1 consumers (batch b). Producers also compute the
// layer1 input projection xw1[t] = h0[t] @ Wx1 + b1 (both Wh0 and Wx1 columns
// register-resident, sharing the same h broadcast loads) and publish it to
// global memory with a fence+flag protocol. Consumers poll the flag and run
// the layer1 recurrence ~8 steps behind.
// ---------------------------------------------------------------------------
__global__ void __launch_bounds__(256, 1)
lstm_pipe(const float* __restrict__ xw0, const float* __restrict__ Wh0,
          const float* __restrict__ Wx1, const float* __restrict__ b1v,
          const float* __restrict__ Wh1,
          float* __restrict__ xw1, int* __restrict__ prog,
          float* __restrict__ c_final) {
    const int b = blockIdx.x & 63;
    const bool producer = blockIdx.x < 64;
    const int g = threadIdx.x;
    const int gtype = g >> 6;

    __shared__ __align__(16) float h_s[F_];
    __shared__ float gbuf[G4_];

    const ulonglong2* h4 = reinterpret_cast<const ulonglong2*>(h_s);

    if (producer) {
        // register-resident columns: Wh0 (gate dot) and Wx1 (layer1 projection)
        ull wA[32], wB[32];
#pragma unroll
        for (int k2 = 0; k2 < 32; k2++) {
            wA[k2] = pk2(Wh0[(size_t)(2 * k2) * G4_ + g],
                         Wh0[(size_t)(2 * k2 + 1) * G4_ + g]);
            wB[k2] = pk2(Wx1[(size_t)(2 * k2) * G4_ + g],
                         Wx1[(size_t)(2 * k2 + 1) * G4_ + g]);
        }
        const float b1g = b1v[g];

        if (g < F_) h_s[g] = 0.0f;
        float c_reg = 0.0f;

        const float* xwb = xw0 + (size_t)b * S_ * G4_ + g;
        float* xwo = xw1 + (size_t)b * S_ * G4_ + g;
        float xwbuf[4];
#pragma unroll
        for (int j = 0; j < 4; j++) xwbuf[j] = xwb[(size_t)j * G4_];
        __syncthreads();

        for (int t = 0; t < S_; t += 4) {
#pragma unroll
            for (int j = 0; j < 4; j++) {
                const int tj = t + j;
                float xv = xwbuf[j];
                int tn = tj + 4;
                if (tn < S_) xwbuf[j] = xwb[(size_t)tn * G4_];

                ull a0 = 0, a1 = 0, a2 = 0, a3 = 0;
                ull q0 = 0, q1 = 0, q2 = 0, q3 = 0;
#pragma unroll
                for (int k4 = 0; k4 < 16; k4 += 2) {
                    ulonglong2 hA = h4[k4];
                    ulonglong2 hB = h4[k4 + 1];
                    a0 = fma2(hA.x, wA[2 * k4 + 0], a0);
                    q0 = fma2(hA.x, wB[2 * k4 + 0], q0);
                    a1 = fma2(hA.y, wA[2 * k4 + 1], a1);
                    q1 = fma2(hA.y, wB[2 * k4 + 1], q1);
                    a2 = fma2(hB.x, wA[2 * k4 + 2], a2);
                    q2 = fma2(hB.x, wB[2 * k4 + 2], q2);
                    a3 = fma2(hB.y, wA[2 * k4 + 3], a3);
                    q3 = fma2(hB.y, wB[2 * k4 + 3], q3);
                }
                a0 = add2(add2(a0, a1), add2(a2, a3));
                q0 = add2(add2(q0, q1), add2(q2, q3));
                float2 sa = upk2(a0);
                float2 sq = upk2(q0);
                float pre = sa.x + sa.y + xv;

                float gv = (gtype == 2) ? tanh_f(pre) : sigmoid_f(pre);
                gbuf[g] = gv;
                // publish xw1[tj-1] = Wx1 . h0[tj-1] + b1 (h_s holds h0[tj-1])
                if (tj > 0) xwo[(size_t)(tj - 1) * G4_] = sq.x + sq.y + b1g;
                __syncthreads();

                if (g < F_) {
                    float iv = gbuf[g];
                    float fv = gbuf[g + 64];
                    float gg = gbuf[g + 128];
                    float ov = gbuf[g + 192];
                    c_reg = fv * c_reg + iv * gg;
                    h_s[g] = ov * tanh_f(c_reg);
                }
                __syncthreads();
            }
            // every 8 steps: make entries [0, t+3] visible, flag count = t+4... 
            // (conservative: flag value t+3 => entries 0..t+2 valid)
            if ((t & 4) && g == 0) {
                __threadfence();
                *(volatile int*)&prog[b] = t + 3;
            }
        }
        // epilogue: publish xw1[S-1] using final h0[S-1]
        {
            ull q0 = 0, q1 = 0, q2 = 0, q3 = 0;
#pragma unroll
            for (int k4 = 0; k4 < 16; k4 += 2) {
                ulonglong2 hA = h4[k4];
                ulonglong2 hB = h4[k4 + 1];
                q0 = fma2(hA.x, wB[2 * k4 + 0], q0);
                q1 = fma2(hA.y, wB[2 * k4 + 1], q1);
                q2 = fma2(hB.x, wB[2 * k4 + 2], q2);
                q3 = fma2(hB.y, wB[2 * k4 + 3], q3);
            }
            q0 = add2(add2(q0, q1), add2(q2, q3));
            float2 sq = upk2(q0);
            xwo[(size_t)(S_ - 1) * G4_] = sq.x + sq.y + b1g;
        }
        __syncthreads();
        if (g == 0) {
            __threadfence();
            *(volatile int*)&prog[b] = S_;
        }
    } else {
        // ---------------- consumer: layer1 recurrence ----------------
        ull w2[32];
#pragma unroll
        for (int k2 = 0; k2 < 32; k2++) {
            w2[k2] = pk2(Wh1[(size_t)(2 * k2) * G4_ + g],
                         Wh1[(size_t)(2 * k2 + 1) * G4_ + g]);
        }

        if (g < F_) h_s[g] = 0.0f;
        float c_reg = 0.0f;

        const float* xwb = xw1 + (size_t)b * S_ * G4_ + g;
        const volatile int* pf = &prog[b];
        int seen = 0;

        // prime prefetch ring: need entries 0..3
        {
            int need = (8 < S_) ? 8 : S_;
            while (seen < need) { seen = *pf; if (seen < need) __nanosleep(64); }
            __threadfence();
        }
        float xwbuf[4];
#pragma unroll
        for (int j = 0; j < 4; j++) xwbuf[j] = __ldcg(xwb + (size_t)j * G4_);
        __syncthreads();

        for (int t = 0; t < S_; t += 4) {
            int need = (t + 8 < S_) ? (t + 8) : S_;
            if (seen < need) {
                while (seen < need) { seen = *pf; if (seen < need) __nanosleep(64); }
                __threadfence();
            }
#pragma unroll
            for (int j = 0; j < 4; j++) {
                float xv = xwbuf[j];
                int tn = t + 4 + j;
                if (tn < S_) xwbuf[j] = __ldcg(xwb + (size_t)tn * G4_);

                ull a0 = 0, a1 = 0, a2 = 0, a3 = 0;
#pragma unroll
                for (int k4 = 0; k4 < 16; k4 += 2) {
                    ulonglong2 hA = h4[k4];
                    ulonglong2 hB = h4[k4 + 1];
                    a0 = fma2(hA.x, w2[2 * k4 + 0], a0);
                    a1 = fma2(hA.y, w2[2 * k4 + 1], a1);
                    a2 = fma2(hB.x, w2[2 * k4 + 2], a2);
                    a3 = fma2(hB.y, w2[2 * k4 + 3], a3);
                }
                a0 = add2(add2(a0, a1), add2(a2, a3));
                float2 sv = upk2(a0);
                float pre = sv.x + sv.y + xv;

                float gv = (gtype == 2) ? tanh_f(pre) : sigmoid_f(pre);
                gbuf[g] = gv;
                __syncthreads();

                if (g < F_) {
                    float iv = gbuf[g];
                    float fv = gbuf[g + 64];
                    float gg = gbuf[g + 128];
                    float ov = gbuf[g + 192];
                    c_reg = fv * c_reg + iv * gg;
                    h_s[g] = ov * tanh_f(c_reg);
                }
                __syncthreads();
            }
        }
        if (g < F_) c_final[b * F_ + g] = c_reg;
    }
}

// ---------------------------------------------------------------------------
// Tiny dense head
// ---------------------------------------------------------------------------
__global__ void dense_head(const float* __restrict__ cf,
                           const float* __restrict__ wd,
                           const float* __restrict__ bd,
                           float* __restrict__ out) {
    int t = threadIdx.x;
    if (t >= B_ * 10) return;
    int b = t / 10, n = t % 10;
    float s = bd[n];
#pragma unroll
    for (int k = 0; k < F_; k++) s += cf[b * F_ + k] * wd[k * 10 + n];
    out[b * 10 + n] = s;
}

// ---------------------------------------------------------------------------
extern "C" void kernel_launch(void* const* d_in, const int* in_sizes, int n_in,
                              void* d_out, int out_size) {
    const float* x       = (const float*)d_in[0];
    const float* conv_w0 = (const float*)d_in[1];
    const float* conv_b0 = (const float*)d_in[2];
    const float* conv_w1 = (const float*)d_in[3];
    const float* conv_b1 = (const float*)d_in[4];
    const float* conv_w2 = (const float*)d_in[5];
    const float* conv_b2 = (const float*)d_in[6];
    const float* Wx0     = (const float*)d_in[7];
    const float* Wh0     = (const float*)d_in[8];
    const float* b0      = (const float*)d_in[9];
    const float* Wx1     = (const float*)d_in[10];
    const float* Wh1     = (const float*)d_in[11];
    const float* b1      = (const float*)d_in[12];
    const float* dense_w = (const float*)d_in[13];
    const float* dense_b = (const float*)d_in[14];
    float* out = (float*)d_out;

    void *pA, *pB, *pXW0, *pXW1, *pPR, *pCF;
    cudaGetSymbolAddress(&pA, g_bufA);
    cudaGetSymbolAddress(&pB, g_bufB);
    cudaGetSymbolAddress(&pXW0, g_xw0);
    cudaGetSymbolAddress(&pXW1, g_xw1);
    cudaGetSymbolAddress(&pPR, g_prog);
    cudaGetSymbolAddress(&pCF, g_cfinal);
    float* bufA = (float*)pA;
    float* bufB = (float*)pB;
    float* xw0  = (float*)pXW0;
    float* xw1  = (float*)pXW1;
    int*   prog = (int*)pPR;
    float* cfin = (float*)pCF;

    dim3 convGrid(S_ / 64, 1, B_);
    dim3 gemmGrid(S_ / 64, G4_ / 64, B_);

    // CNN stack
    conv_gemm<3, true><<<convGrid, 256>>>(x, conv_w0, conv_b0, bufA, 128, 64);
    conv_gemm<3, true><<<convGrid, 256>>>(bufA, conv_w1, conv_b1, bufB, 64, 64);
    conv_gemm<3, true><<<convGrid, 256>>>(bufB, conv_w2, conv_b2, bufA, 64, 64);

    // LSTM layer0 input projection (big parallel GEMM)
    conv_gemm<1, false><<<gemmGrid, 256>>>(bufA, Wx0, b0, xw0, 64, 256);

    // Pipelined 2-layer recurrence (layer1 xw computed by producers on the fly)
    lstm_pipe<<<2 * B_, 256>>>(xw0, Wh0, Wx1, b1, Wh1, xw1, prog, cfin);

    // Dense head
    dense_head<<<1, B_ * 10>>>(cfin, dense_w, dense_b, out);
}